// round 1
// baseline (speedup 1.0000x reference)
#include <cuda_runtime.h>
#include <math.h>

// Problem dims (fixed by the reference)
#define Bc  4
#define Tc  1024
#define Ec  512
#define Hc  1024
#define Kc  512
#define Vdc 512
#define Vc  32000
#define MT  (Bc * Tc)   // 4096 flattened (b,t)

// ---------------- scratch (device globals; no allocations) ----------------
__device__ float gX [MT * Ec];     // gathered embeddings
__device__ float gXP[MT * Hc];     // xp = x @ Wi^T + bi
__device__ float gHID[MT * Hc];    // fallback hidden
__device__ float gOUTS[MT * Hc];   // fallback outs
__device__ float gQ [MT * Kc];
__device__ float gK [MT * Kc];
__device__ float gVT[MT * Vdc];    // v stored transposed per batch: [B][Vd][T]
__device__ float gS [Bc * Tc * Tc];
__device__ float gA [MT * Vdc];
__device__ float gAO[MT * Hc];

__device__ unsigned g_cnt = 0;
__device__ unsigned g_gen = 0;

// ---------------- grid barrier (all blocks co-resident) ----------------
__device__ __forceinline__ void grid_barrier(int nblocks) {
    __syncthreads();
    if (threadIdx.x == 0) {
        unsigned gen = *((volatile unsigned*)&g_gen);
        __threadfence();
        unsigned arrived = atomicAdd(&g_cnt, 1u);
        if (arrived == (unsigned)(nblocks - 1)) {
            g_cnt = 0;
            __threadfence();
            atomicAdd(&g_gen, 1u);
        } else {
            while (*((volatile unsigned*)&g_gen) == gen) { }
        }
        __threadfence();
    }
    __syncthreads();
}

// ---------------- generic tiled GEMM: C = alpha * (A . B^T + bias) ----------------
// A: [M, Kd] row-major, B: [N, Kd] row-major (weight layout), C: [M, N]
// batched via blockIdx.z with strides. VT_STORE=1 writes C transposed per batch
// into a [B][Vd][T] tensor (used for V).
template <int VT_STORE>
__global__ __launch_bounds__(256)
void gemm_abt(const float* __restrict__ A, const float* __restrict__ Bm,
              const float* __restrict__ bias, float* __restrict__ C,
              int M, int N, int Kd, float alpha,
              long sA, long sB, long sC)
{
    __shared__ float As[8][128];
    __shared__ float Bs[8][128];

    int z = blockIdx.z;
    const float* Ab = A  + (long)z * sA;
    const float* Bb = Bm + (long)z * sB;
    float*       Cb = C  + (long)z * sC;

    int m0 = blockIdx.y * 128;
    int n0 = blockIdx.x * 128;
    int tid = threadIdx.x;
    int mr = tid >> 4;        // 0..15
    int nr = tid & 15;        // 0..15

    int lrow = tid >> 1;            // 0..127
    int lk   = (tid & 1) * 4;       // 0 or 4

    const float* Aptr = Ab + (long)(m0 + lrow) * Kd + lk;
    const float* Bptr = Bb + (long)(n0 + lrow) * Kd + lk;

    float acc[8][8];
#pragma unroll
    for (int i = 0; i < 8; i++)
#pragma unroll
        for (int j = 0; j < 8; j++) acc[i][j] = 0.f;

    for (int k0 = 0; k0 < Kd; k0 += 8) {
        float4 av = *(const float4*)(Aptr + k0);
        float4 bv = *(const float4*)(Bptr + k0);
        __syncthreads();
        As[lk + 0][lrow] = av.x; As[lk + 1][lrow] = av.y;
        As[lk + 2][lrow] = av.z; As[lk + 3][lrow] = av.w;
        Bs[lk + 0][lrow] = bv.x; Bs[lk + 1][lrow] = bv.y;
        Bs[lk + 2][lrow] = bv.z; Bs[lk + 3][lrow] = bv.w;
        __syncthreads();
#pragma unroll
        for (int kk = 0; kk < 8; kk++) {
            float a[8], b[8];
            *(float4*)(a)     = *(const float4*)&As[kk][mr * 8];
            *(float4*)(a + 4) = *(const float4*)&As[kk][mr * 8 + 4];
            *(float4*)(b)     = *(const float4*)&Bs[kk][nr * 8];
            *(float4*)(b + 4) = *(const float4*)&Bs[kk][nr * 8 + 4];
#pragma unroll
            for (int i = 0; i < 8; i++)
#pragma unroll
                for (int j = 0; j < 8; j++)
                    acc[i][j] += a[i] * b[j];
        }
    }

    // epilogue
#pragma unroll
    for (int i = 0; i < 8; i++) {
        long m = m0 + mr * 8 + i;
        if (VT_STORE) {
#pragma unroll
            for (int j = 0; j < 8; j++) {
                int n = n0 + nr * 8 + j;
                float vb = bias ? bias[n] : 0.f;
                float v = alpha * (acc[i][j] + vb);
                int bb = (int)(m >> 10);
                int tt = (int)(m & 1023);
                Cb[((long)(bb * Vdc + n) << 10) + tt] = v;
            }
        } else {
            float out[8];
#pragma unroll
            for (int j = 0; j < 8; j++) {
                int n = n0 + nr * 8 + j;
                float vb = bias ? bias[n] : 0.f;
                out[j] = alpha * (acc[i][j] + vb);
            }
            float* dst = &Cb[m * (long)N + n0 + nr * 8];
            *(float4*)(dst)     = *(float4*)(out);
            *(float4*)(dst + 4) = *(float4*)(out + 4);
        }
    }
}

// ---------------- embedding gather ----------------
__global__ void gather_emb(const int* __restrict__ tok,
                           const float* __restrict__ emb,
                           float* __restrict__ X)
{
    int m = blockIdx.x;
    int v = tok[m];
    const float4* src = (const float4*)(emb + (long)v * Ec);
    float4*       dst = (float4*)(X + (long)m * Ec);
    dst[threadIdx.x] = src[threadIdx.x];   // 128 threads * float4 = 512
}

// ---------------- RNN recurrence (persistent, grid-barrier per step) ----------------
// 128 blocks x 256 threads. Each warp owns ONE output row of Wh (in registers),
// block covers rows [blockIdx.x*8, +8). h_prev broadcast via batch-interleaved smem.
#define RNN_BLOCKS 128
__global__ __launch_bounds__(256)
void rnn_kernel(const float* __restrict__ xp, const float* __restrict__ Wh,
                const float* __restrict__ bh, float* hidden)
{
    __shared__ float hp[Hc * Bc];   // hp[h*4 + b], 16 KB
    int tid  = threadIdx.x;
    int lane = tid & 31;
    int warp = tid >> 5;
    int row  = blockIdx.x * 8 + warp;   // 0..1023

    // Wh row resident in registers: wh[jj] = Wh[row][jj*32 + lane]
    float wh[32];
#pragma unroll
    for (int jj = 0; jj < 32; jj++)
        wh[jj] = Wh[(long)row * Hc + jj * 32 + lane];
    float bias = bh[row];

    for (int t = 0; t < Tc; t++) {
        if (t == 0) {
            for (int i = tid; i < Hc * Bc; i += 256) hp[i] = 0.f;
        } else {
            for (int i = tid; i < Hc; i += 256) {
                float4 v;
                v.x = hidden[((long)0 * Tc + (t - 1)) * Hc + i];
                v.y = hidden[((long)1 * Tc + (t - 1)) * Hc + i];
                v.z = hidden[((long)2 * Tc + (t - 1)) * Hc + i];
                v.w = hidden[((long)3 * Tc + (t - 1)) * Hc + i];
                *(float4*)&hp[i * 4] = v;
            }
        }
        __syncthreads();

        float a0 = 0.f, a1 = 0.f, a2 = 0.f, a3 = 0.f;
#pragma unroll
        for (int jj = 0; jj < 32; jj++) {
            float4 h4 = *(const float4*)&hp[(jj * 32 + lane) * 4];
            float w = wh[jj];
            a0 += w * h4.x; a1 += w * h4.y; a2 += w * h4.z; a3 += w * h4.w;
        }
#pragma unroll
        for (int off = 16; off; off >>= 1) {
            a0 += __shfl_xor_sync(0xffffffffu, a0, off);
            a1 += __shfl_xor_sync(0xffffffffu, a1, off);
            a2 += __shfl_xor_sync(0xffffffffu, a2, off);
            a3 += __shfl_xor_sync(0xffffffffu, a3, off);
        }
        if (lane < 4) {
            float s = (lane == 0) ? a0 : (lane == 1) ? a1 : (lane == 2) ? a2 : a3;
            long idx = ((long)lane * Tc + t) * Hc + row;
            float v = xp[idx] + s + bias;
            hidden[idx] = fmaxf(v, 0.f);
        }
        grid_barrier(RNN_BLOCKS);
    }
}

// ---------------- causal softmax (in place, one block per row) ----------------
__global__ __launch_bounds__(256)
void softmax_causal(float* __restrict__ S)
{
    long rowid = blockIdx.x;            // b*T + t
    int  t = (int)(rowid & (Tc - 1));
    float* row = S + rowid * Tc;
    int tid = threadIdx.x;
    int lane = tid & 31, wid = tid >> 5;
    __shared__ float red[8];
    __shared__ float mshared, sshared;
    int L = t + 1;

    float m = -1e30f;
    for (int i = tid; i < L; i += 256) m = fmaxf(m, row[i]);
#pragma unroll
    for (int off = 16; off; off >>= 1) m = fmaxf(m, __shfl_xor_sync(0xffffffffu, m, off));
    if (lane == 0) red[wid] = m;
    __syncthreads();
    if (tid == 0) {
        float mm = red[0];
        for (int w = 1; w < 8; w++) mm = fmaxf(mm, red[w]);
        mshared = mm;
    }
    __syncthreads();
    m = mshared;

    float s = 0.f;
    for (int i = tid; i < L; i += 256) s += expf(row[i] - m);
#pragma unroll
    for (int off = 16; off; off >>= 1) s += __shfl_xor_sync(0xffffffffu, s, off);
    __syncthreads();   // protect red reuse
    if (lane == 0) red[wid] = s;
    __syncthreads();
    if (tid == 0) {
        float ss = 0.f;
        for (int w = 0; w < 8; w++) ss += red[w];
        sshared = 1.0f / ss;
    }
    __syncthreads();
    float inv = sshared;

    for (int i = tid; i < Tc; i += 256)
        row[i] = (i < L) ? expf(row[i] - m) * inv : 0.0f;
}

// ---------------- launch ----------------
extern "C" void kernel_launch(void* const* d_in, const int* in_sizes, int n_in,
                              void* d_out, int out_size)
{
    const int*   tok = (const int*)  d_in[0];
    const float* emb = (const float*)d_in[1];
    const float* Wi  = (const float*)d_in[2];
    const float* bi  = (const float*)d_in[3];
    const float* Wh  = (const float*)d_in[4];
    const float* bh  = (const float*)d_in[5];
    const float* Wro = (const float*)d_in[6];
    const float* bro = (const float*)d_in[7];
    const float* Wq  = (const float*)d_in[8];
    const float* bq  = (const float*)d_in[9];
    const float* Wk  = (const float*)d_in[10];
    const float* bk  = (const float*)d_in[11];
    const float* Wv  = (const float*)d_in[12];
    const float* bv  = (const float*)d_in[13];
    const float* Wao = (const float*)d_in[14];
    const float* bao = (const float*)d_in[15];
    const float* Wlm = (const float*)d_in[16];
    const float* blm = (const float*)d_in[17];
    float* out = (float*)d_out;

    float *x, *xp, *q, *k, *vt, *s, *a, *ao, *hidF, *outsF;
    cudaGetSymbolAddress((void**)&x,    gX);
    cudaGetSymbolAddress((void**)&xp,   gXP);
    cudaGetSymbolAddress((void**)&q,    gQ);
    cudaGetSymbolAddress((void**)&k,    gK);
    cudaGetSymbolAddress((void**)&vt,   gVT);
    cudaGetSymbolAddress((void**)&s,    gS);
    cudaGetSymbolAddress((void**)&a,    gA);
    cudaGetSymbolAddress((void**)&ao,   gAO);
    cudaGetSymbolAddress((void**)&hidF, gHID);
    cudaGetSymbolAddress((void**)&outsF, gOUTS);

    // output layout: [logits | hidden | outs] if out_size matches, else logits only
    long fullsz = (long)MT * Vc + 2L * MT * Hc;
    float* hidden = hidF;
    float* outs   = outsF;
    if ((long)out_size >= fullsz) {
        hidden = out + (long)MT * Vc;
        outs   = hidden + (long)MT * Hc;
    }

    const float qscale = 1.0f / sqrtf((float)Kc);

    // 1) gather embeddings
    gather_emb<<<MT, 128>>>(tok, emb, x);

    // 2) xp = x @ Wi^T + bi       [4096,512]x[1024,512]^T
    gemm_abt<0><<<dim3(Hc / 128, MT / 128, 1), 256>>>(x, Wi, bi, xp, MT, Hc, Ec, 1.f, 0, 0, 0);

    // 3) RNN recurrence -> hidden
    rnn_kernel<<<RNN_BLOCKS, 256>>>(xp, Wh, bh, hidden);

    // 4) outs = hidden @ Wro^T + bro
    gemm_abt<0><<<dim3(Hc / 128, MT / 128, 1), 256>>>(hidden, Wro, bro, outs, MT, Hc, Hc, 1.f, 0, 0, 0);

    // 5) q, k, v projections
    gemm_abt<0><<<dim3(Kc / 128, MT / 128, 1), 256>>>(outs, Wq, bq, q, MT, Kc, Hc, qscale, 0, 0, 0);
    gemm_abt<0><<<dim3(Kc / 128, MT / 128, 1), 256>>>(outs, Wk, bk, k, MT, Kc, Hc, 1.f, 0, 0, 0);
    gemm_abt<1><<<dim3(Vdc / 128, MT / 128, 1), 256>>>(outs, Wv, bv, vt, MT, Vdc, Hc, 1.f, 0, 0, 0);

    // 6) scores[b] = q[b] @ k[b]^T   (batched over B)
    gemm_abt<0><<<dim3(Tc / 128, Tc / 128, Bc), 256>>>(q, k, nullptr, s,
        Tc, Tc, Kc, 1.f, (long)Tc * Kc, (long)Tc * Kc, (long)Tc * Tc);

    // 7) causal softmax in place
    softmax_causal<<<MT, 256>>>(s);

    // 8) attn[b] = w[b] @ v[b]  via vT:  [T,T]x[Vd,T]^T
    gemm_abt<0><<<dim3(Vdc / 128, Tc / 128, Bc), 256>>>(s, vt, nullptr, a,
        Tc, Vdc, Tc, 1.f, (long)Tc * Tc, (long)Vdc * Tc, (long)Tc * Vdc);

    // 9) attn_out = attn @ Wao^T + bao
    gemm_abt<0><<<dim3(Hc / 128, MT / 128, 1), 256>>>(a, Wao, bao, ao, MT, Hc, Vdc, 1.f, 0, 0, 0);

    // 10) logits = attn_out @ Wlm^T + blm
    gemm_abt<0><<<dim3(Vc / 128, MT / 128, 1), 256>>>(ao, Wlm, blm, out, MT, Vc, Hc, 1.f, 0, 0, 0);
}

// round 2
// speedup vs baseline: 1.4914x; 1.4914x over previous
#include <cuda_runtime.h>
#include <cuda_bf16.h>
#include <math.h>

#define Bc  4
#define Tc  1024
#define Ec  512
#define Hc  1024
#define Kc  512
#define Vdc 512
#define Vc  32000
#define MT  (Bc * Tc)   // 4096

typedef unsigned int u32;

// ---------------- fp32 scratch ----------------
__device__ float gXP  [MT * Hc];
__device__ float gHIDf[MT * Hc];
__device__ float gOUTSf[MT * Hc];
__device__ float gS   [Bc * Tc * Tc];

// ---------------- bf16 hi/lo scratch ----------------
__device__ __nv_bfloat16 gXh[MT*Ec],  gXl[MT*Ec];
__device__ __nv_bfloat16 gHh[MT*Hc],  gHl[MT*Hc];
__device__ __nv_bfloat16 gOh[MT*Hc],  gOl[MT*Hc];
__device__ __nv_bfloat16 gQh[MT*Kc],  gQl[MT*Kc];
__device__ __nv_bfloat16 gKh2[MT*Kc], gKl2[MT*Kc];
__device__ __nv_bfloat16 gVh[MT*Vdc], gVl[MT*Vdc];    // transposed per batch [B][Vd][T]
__device__ __nv_bfloat16 gSh[Bc*Tc*Tc], gSl[Bc*Tc*Tc];
__device__ __nv_bfloat16 gAh2[MT*Vdc], gAl2[MT*Vdc];
__device__ __nv_bfloat16 gAOh[MT*Hc],  gAOl[MT*Hc];
// weights
__device__ __nv_bfloat16 gWih[Hc*Ec],  gWil[Hc*Ec];
__device__ __nv_bfloat16 gWroh[Hc*Hc], gWrol[Hc*Hc];
__device__ __nv_bfloat16 gWqh[Kc*Hc],  gWql[Kc*Hc];
__device__ __nv_bfloat16 gWkh[Kc*Hc],  gWkl[Kc*Hc];
__device__ __nv_bfloat16 gWvh[Vdc*Hc], gWvl[Vdc*Hc];
__device__ __nv_bfloat16 gWaoh[Hc*Vdc],gWaol[Hc*Vdc];
__device__ __nv_bfloat16 gWlmh[(size_t)Vc*Hc], gWlml[(size_t)Vc*Hc];

__device__ unsigned g_cnt = 0;
__device__ unsigned g_gen = 0;

// ---------------- helpers ----------------
__device__ __forceinline__ void split1(float x, __nv_bfloat16& h, __nv_bfloat16& l) {
    h = __float2bfloat16_rn(x);
    l = __float2bfloat16_rn(x - __bfloat162float(h));
}

__device__ __forceinline__ void mma_bf16(float* c, const u32* a, const u32* b) {
    asm volatile(
        "mma.sync.aligned.m16n8k16.row.col.f32.bf16.bf16.f32 "
        "{%0,%1,%2,%3}, {%4,%5,%6,%7}, {%8,%9}, {%0,%1,%2,%3};\n"
        : "+f"(c[0]), "+f"(c[1]), "+f"(c[2]), "+f"(c[3])
        : "r"(a[0]), "r"(a[1]), "r"(a[2]), "r"(a[3]), "r"(b[0]), "r"(b[1]));
}

// ---------------- grid barrier ----------------
__device__ __forceinline__ void grid_barrier(int nblocks) {
    __syncthreads();
    if (threadIdx.x == 0) {
        unsigned gen = *((volatile unsigned*)&g_gen);
        __threadfence();
        unsigned arrived = atomicAdd(&g_cnt, 1u);
        if (arrived == (unsigned)(nblocks - 1)) {
            g_cnt = 0;
            __threadfence();
            atomicAdd(&g_gen, 1u);
        } else {
            while (*((volatile unsigned*)&g_gen) == gen) { }
        }
        __threadfence();
    }
    __syncthreads();
}

// ---------------- split conversion (fp32 -> bf16 hi/lo) ----------------
__global__ void conv_split(const float* __restrict__ s, __nv_bfloat16* __restrict__ h,
                           __nv_bfloat16* __restrict__ l, int n4)
{
    int i = blockIdx.x * blockDim.x + threadIdx.x;
    if (i >= n4) return;
    float4 v = ((const float4*)s)[i];
    __nv_bfloat16 hh[4], ll[4];
    split1(v.x, hh[0], ll[0]);
    split1(v.y, hh[1], ll[1]);
    split1(v.z, hh[2], ll[2]);
    split1(v.w, hh[3], ll[3]);
    *(uint2*)(h + 4 * (size_t)i) = *(uint2*)hh;
    *(uint2*)(l + 4 * (size_t)i) = *(uint2*)ll;
}

// ---------------- embedding gather + split ----------------
__global__ void gather_emb(const int* __restrict__ tok, const float* __restrict__ emb,
                           __nv_bfloat16* __restrict__ xh, __nv_bfloat16* __restrict__ xl)
{
    int m = blockIdx.x;
    int v = tok[m];
    float4 val = ((const float4*)(emb + (size_t)v * Ec))[threadIdx.x];
    __nv_bfloat16 hh[4], ll[4];
    split1(val.x, hh[0], ll[0]);
    split1(val.y, hh[1], ll[1]);
    split1(val.z, hh[2], ll[2]);
    split1(val.w, hh[3], ll[3]);
    size_t off = (size_t)m * Ec + threadIdx.x * 4;
    *(uint2*)(xh + off) = *(uint2*)hh;
    *(uint2*)(xl + off) = *(uint2*)ll;
}

// ---------------- split-bf16 MMA GEMM ----------------
// C = alpha * (A . B^T + bias),  A:[M,K] (hi/lo), B:[N,K] (hi/lo)
// outputs: Cf (fp32, optional), Ch/Cl (bf16 split, optional)
// VT=1: store bf16 transposed per batch into [B][Vd][T] (v projection)
// Block 128x128x16, 4 warps of 64x64, double-buffered smem.
template <int VT>
__global__ __launch_bounds__(128)
void gemm_mma(const __nv_bfloat16* __restrict__ Ah, const __nv_bfloat16* __restrict__ Al,
              const __nv_bfloat16* __restrict__ Bh, const __nv_bfloat16* __restrict__ Bl,
              const float* __restrict__ bias,
              float* __restrict__ Cf, __nv_bfloat16* __restrict__ Ch, __nv_bfloat16* __restrict__ Cl,
              int M, int N, int K, float alpha,
              long sA, long sB, long sC)
{
    // [stage][array: Ah,Al,Bh,Bl][128 rows * 12 words]  = 49152 bytes
    __shared__ u32 sm[2][4][128 * 12];

    int z = blockIdx.z;
    const __nv_bfloat16* Abh = Ah + (size_t)z * sA;
    const __nv_bfloat16* Abl = Al + (size_t)z * sA;
    const __nv_bfloat16* Bbh = Bh + (size_t)z * sB;
    const __nv_bfloat16* Bbl = Bl + (size_t)z * sB;
    float* Cfb = Cf ? Cf + (size_t)z * sC : (float*)0;
    __nv_bfloat16* Chb = Ch ? Ch + (size_t)z * sC : (__nv_bfloat16*)0;
    __nv_bfloat16* Clb = Cl ? Cl + (size_t)z * sC : (__nv_bfloat16*)0;

    int m0 = blockIdx.x * 128;
    int n0 = blockIdx.y * 128;
    int tid  = threadIdx.x;
    int lane = tid & 31;
    int warp = tid >> 5;
    int wm = (warp >> 1) * 64;
    int wn = (warp & 1) * 64;
    int g = lane >> 2;
    int t = lane & 3;

    float acc[4][8][4];
#pragma unroll
    for (int f = 0; f < 4; f++)
#pragma unroll
        for (int n = 0; n < 8; n++)
#pragma unroll
            for (int r = 0; r < 4; r++) acc[f][n][r] = 0.f;

    const uint4* pAh = (const uint4*)(Abh + (size_t)(m0 + tid) * K);
    const uint4* pAl = (const uint4*)(Abl + (size_t)(m0 + tid) * K);
    const uint4* pBh = (const uint4*)(Bbh + (size_t)(n0 + tid) * K);
    const uint4* pBl = (const uint4*)(Bbl + (size_t)(n0 + tid) * K);

    // preload stage 0 (k0 = 0)
    {
        uint4* dA0 = (uint4*)&sm[0][0][tid * 12];
        uint4* dA1 = (uint4*)&sm[0][1][tid * 12];
        uint4* dB0 = (uint4*)&sm[0][2][tid * 12];
        uint4* dB1 = (uint4*)&sm[0][3][tid * 12];
        dA0[0] = pAh[0]; dA0[1] = pAh[1];
        dA1[0] = pAl[0]; dA1[1] = pAl[1];
        dB0[0] = pBh[0]; dB0[1] = pBh[1];
        dB1[0] = pBl[0]; dB1[1] = pBl[1];
    }
    __syncthreads();

    int nIter = K >> 4;
    for (int it = 0; it < nIter; it++) {
        int st = it & 1;
        uint4 pf[8];
        bool has = (it + 1) < nIter;
        if (has) {
            int kb = (it + 1) * 2;
            pf[0] = pAh[kb]; pf[1] = pAh[kb + 1];
            pf[2] = pAl[kb]; pf[3] = pAl[kb + 1];
            pf[4] = pBh[kb]; pf[5] = pBh[kb + 1];
            pf[6] = pBl[kb]; pf[7] = pBl[kb + 1];
        }

        const u32* SAh = sm[st][0];
        const u32* SAl = sm[st][1];
        const u32* SBh = sm[st][2];
        const u32* SBl = sm[st][3];

        u32 ah[4][4], al[4][4], bb[8][2];
#pragma unroll
        for (int f = 0; f < 4; f++) {
            int rb = (wm + f * 16 + g) * 12 + t;
            ah[f][0] = SAh[rb];       ah[f][1] = SAh[rb + 96];
            ah[f][2] = SAh[rb + 4];   ah[f][3] = SAh[rb + 100];
            al[f][0] = SAl[rb];       al[f][1] = SAl[rb + 96];
            al[f][2] = SAl[rb + 4];   al[f][3] = SAl[rb + 100];
        }
#pragma unroll
        for (int n = 0; n < 8; n++) {
            int rb = (wn + n * 8 + g) * 12 + t;
            bb[n][0] = SBh[rb]; bb[n][1] = SBh[rb + 4];
        }
#pragma unroll
        for (int f = 0; f < 4; f++)
#pragma unroll
            for (int n = 0; n < 8; n++) mma_bf16(acc[f][n], ah[f], bb[n]);
#pragma unroll
        for (int f = 0; f < 4; f++)
#pragma unroll
            for (int n = 0; n < 8; n++) mma_bf16(acc[f][n], al[f], bb[n]);
#pragma unroll
        for (int n = 0; n < 8; n++) {
            int rb = (wn + n * 8 + g) * 12 + t;
            bb[n][0] = SBl[rb]; bb[n][1] = SBl[rb + 4];
        }
#pragma unroll
        for (int f = 0; f < 4; f++)
#pragma unroll
            for (int n = 0; n < 8; n++) mma_bf16(acc[f][n], ah[f], bb[n]);

        if (has) {
            int ns = st ^ 1;
            uint4* dA0 = (uint4*)&sm[ns][0][tid * 12];
            uint4* dA1 = (uint4*)&sm[ns][1][tid * 12];
            uint4* dB0 = (uint4*)&sm[ns][2][tid * 12];
            uint4* dB1 = (uint4*)&sm[ns][3][tid * 12];
            dA0[0] = pf[0]; dA0[1] = pf[1];
            dA1[0] = pf[2]; dA1[1] = pf[3];
            dB0[0] = pf[4]; dB0[1] = pf[5];
            dB1[0] = pf[6]; dB1[1] = pf[7];
        }
        __syncthreads();
    }

    // ---------------- epilogue ----------------
#pragma unroll
    for (int f = 0; f < 4; f++) {
        int r0 = m0 + wm + f * 16 + g;
        int r1 = r0 + 8;
#pragma unroll
        for (int n = 0; n < 8; n++) {
            int c = n0 + wn + n * 8 + 2 * t;
            float b0 = 0.f, b1 = 0.f;
            if (bias) { b0 = bias[c]; b1 = bias[c + 1]; }
            float v00 = alpha * (acc[f][n][0] + b0);
            float v01 = alpha * (acc[f][n][1] + b1);
            float v10 = alpha * (acc[f][n][2] + b0);
            float v11 = alpha * (acc[f][n][3] + b1);
            if (VT) {
                // transposed bf16 store: row r -> (batch, time), col c -> Vd index
                int bb0 = r0 >> 10, tt0 = r0 & 1023;
                int bb1 = r1 >> 10, tt1 = r1 & 1023;
                size_t i00 = ((size_t)(bb0 * Vdc + c) << 10) + tt0;
                size_t i01 = ((size_t)(bb0 * Vdc + c + 1) << 10) + tt0;
                size_t i10 = ((size_t)(bb1 * Vdc + c) << 10) + tt1;
                size_t i11 = ((size_t)(bb1 * Vdc + c + 1) << 10) + tt1;
                __nv_bfloat16 h, l;
                split1(v00, h, l); Chb[i00] = h; Clb[i00] = l;
                split1(v01, h, l); Chb[i01] = h; Clb[i01] = l;
                split1(v10, h, l); Chb[i10] = h; Clb[i10] = l;
                split1(v11, h, l); Chb[i11] = h; Clb[i11] = l;
            } else {
                if (Cfb) {
                    *(float2*)&Cfb[(size_t)r0 * N + c] = make_float2(v00, v01);
                    *(float2*)&Cfb[(size_t)r1 * N + c] = make_float2(v10, v11);
                }
                if (Chb) {
                    __nv_bfloat16 h0, l0, h1, l1;
                    split1(v00, h0, l0); split1(v01, h1, l1);
                    ((__nv_bfloat162*)Chb)[((size_t)r0 * N + c) >> 1] = __halves2bfloat162(h0, h1);
                    ((__nv_bfloat162*)Clb)[((size_t)r0 * N + c) >> 1] = __halves2bfloat162(l0, l1);
                    split1(v10, h0, l0); split1(v11, h1, l1);
                    ((__nv_bfloat162*)Chb)[((size_t)r1 * N + c) >> 1] = __halves2bfloat162(h0, h1);
                    ((__nv_bfloat162*)Clb)[((size_t)r1 * N + c) >> 1] = __halves2bfloat162(l0, l1);
                }
            }
        }
    }
}

// ---------------- RNN recurrence (persistent, grid-barrier per step) ----------------
#define RNN_BLOCKS 128
__global__ __launch_bounds__(256)
void rnn_kernel(const float* __restrict__ xp, const float* __restrict__ Wh,
                const float* __restrict__ bh, float* hidden,
                __nv_bfloat16* __restrict__ hh_out, __nv_bfloat16* __restrict__ hl_out)
{
    __shared__ float hp[Hc * Bc];   // hp[h*4 + b]
    int tid  = threadIdx.x;
    int lane = tid & 31;
    int warp = tid >> 5;
    int row  = blockIdx.x * 8 + warp;

    float wh[32];
#pragma unroll
    for (int jj = 0; jj < 32; jj++)
        wh[jj] = Wh[(size_t)row * Hc + jj * 32 + lane];
    float bias = bh[row];

    for (int tstep = 0; tstep < Tc; tstep++) {
        if (tstep == 0) {
            for (int i = tid; i < Hc * Bc; i += 256) hp[i] = 0.f;
        } else {
            for (int i = tid; i < Hc; i += 256) {
                float4 v;
                v.x = hidden[((size_t)0 * Tc + (tstep - 1)) * Hc + i];
                v.y = hidden[((size_t)1 * Tc + (tstep - 1)) * Hc + i];
                v.z = hidden[((size_t)2 * Tc + (tstep - 1)) * Hc + i];
                v.w = hidden[((size_t)3 * Tc + (tstep - 1)) * Hc + i];
                *(float4*)&hp[i * 4] = v;
            }
        }
        __syncthreads();

        float a0 = 0.f, a1 = 0.f, a2 = 0.f, a3 = 0.f;
#pragma unroll
        for (int jj = 0; jj < 32; jj++) {
            float4 h4 = *(const float4*)&hp[(jj * 32 + lane) * 4];
            float w = wh[jj];
            a0 += w * h4.x; a1 += w * h4.y; a2 += w * h4.z; a3 += w * h4.w;
        }
#pragma unroll
        for (int off = 16; off; off >>= 1) {
            a0 += __shfl_xor_sync(0xffffffffu, a0, off);
            a1 += __shfl_xor_sync(0xffffffffu, a1, off);
            a2 += __shfl_xor_sync(0xffffffffu, a2, off);
            a3 += __shfl_xor_sync(0xffffffffu, a3, off);
        }
        if (lane < 4) {
            float s = (lane == 0) ? a0 : (lane == 1) ? a1 : (lane == 2) ? a2 : a3;
            size_t idx = ((size_t)lane * Tc + tstep) * Hc + row;
            float v = xp[idx] + s + bias;
            v = fmaxf(v, 0.f);
            hidden[idx] = v;
            __nv_bfloat16 h, l;
            split1(v, h, l);
            hh_out[idx] = h; hl_out[idx] = l;
        }
        grid_barrier(RNN_BLOCKS);
    }
}

// ---------------- causal softmax: fp32 in, bf16 hi/lo out ----------------
__global__ __launch_bounds__(256)
void softmax_causal(const float* __restrict__ S,
                    __nv_bfloat16* __restrict__ Ph, __nv_bfloat16* __restrict__ Pl)
{
    size_t rowid = blockIdx.x;
    int  tq = (int)(rowid & (Tc - 1));
    const float* row = S + rowid * Tc;
    int tid = threadIdx.x;
    int lane = tid & 31, wid = tid >> 5;
    __shared__ float red[8];
    __shared__ float mshared, sshared;
    int L = tq + 1;

    float m = -1e30f;
    for (int i = tid; i < L; i += 256) m = fmaxf(m, row[i]);
#pragma unroll
    for (int off = 16; off; off >>= 1) m = fmaxf(m, __shfl_xor_sync(0xffffffffu, m, off));
    if (lane == 0) red[wid] = m;
    __syncthreads();
    if (tid == 0) {
        float mm = red[0];
        for (int w = 1; w < 8; w++) mm = fmaxf(mm, red[w]);
        mshared = mm;
    }
    __syncthreads();
    m = mshared;

    float s = 0.f;
    for (int i = tid; i < L; i += 256) s += expf(row[i] - m);
#pragma unroll
    for (int off = 16; off; off >>= 1) s += __shfl_xor_sync(0xffffffffu, s, off);
    __syncthreads();
    if (lane == 0) red[wid] = s;
    __syncthreads();
    if (tid == 0) {
        float ss = 0.f;
        for (int w = 0; w < 8; w++) ss += red[w];
        sshared = 1.0f / ss;
    }
    __syncthreads();
    float inv = sshared;

    for (int i = tid; i < Tc; i += 256) {
        float p = (i < L) ? expf(row[i] - m) * inv : 0.0f;
        __nv_bfloat16 h, l;
        split1(p, h, l);
        Ph[rowid * Tc + i] = h;
        Pl[rowid * Tc + i] = l;
    }
}

// ---------------- launch ----------------
extern "C" void kernel_launch(void* const* d_in, const int* in_sizes, int n_in,
                              void* d_out, int out_size)
{
    const int*   tok = (const int*)  d_in[0];
    const float* emb = (const float*)d_in[1];
    const float* Wi  = (const float*)d_in[2];
    const float* bi  = (const float*)d_in[3];
    const float* Wh  = (const float*)d_in[4];
    const float* bh  = (const float*)d_in[5];
    const float* Wro = (const float*)d_in[6];
    const float* bro = (const float*)d_in[7];
    const float* Wq  = (const float*)d_in[8];
    const float* bq  = (const float*)d_in[9];
    const float* Wk  = (const float*)d_in[10];
    const float* bk  = (const float*)d_in[11];
    const float* Wv  = (const float*)d_in[12];
    const float* bv  = (const float*)d_in[13];
    const float* Wao = (const float*)d_in[14];
    const float* bao = (const float*)d_in[15];
    const float* Wlm = (const float*)d_in[16];
    const float* blm = (const float*)d_in[17];
    float* out = (float*)d_out;

    // resolve scratch symbols
    float *xp, *s, *hidF, *outsF;
    cudaGetSymbolAddress((void**)&xp,    gXP);
    cudaGetSymbolAddress((void**)&s,     gS);
    cudaGetSymbolAddress((void**)&hidF,  gHIDf);
    cudaGetSymbolAddress((void**)&outsF, gOUTSf);

    __nv_bfloat16 *xh,*xl,*hh,*hl,*oh,*ol,*qh,*ql,*kh,*kl,*vh,*vl,*sh,*sl,*ah,*al,*aoh,*aol;
    cudaGetSymbolAddress((void**)&xh, gXh);   cudaGetSymbolAddress((void**)&xl, gXl);
    cudaGetSymbolAddress((void**)&hh, gHh);   cudaGetSymbolAddress((void**)&hl, gHl);
    cudaGetSymbolAddress((void**)&oh, gOh);   cudaGetSymbolAddress((void**)&ol, gOl);
    cudaGetSymbolAddress((void**)&qh, gQh);   cudaGetSymbolAddress((void**)&ql, gQl);
    cudaGetSymbolAddress((void**)&kh, gKh2);  cudaGetSymbolAddress((void**)&kl, gKl2);
    cudaGetSymbolAddress((void**)&vh, gVh);   cudaGetSymbolAddress((void**)&vl, gVl);
    cudaGetSymbolAddress((void**)&sh, gSh);   cudaGetSymbolAddress((void**)&sl, gSl);
    cudaGetSymbolAddress((void**)&ah, gAh2);  cudaGetSymbolAddress((void**)&al, gAl2);
    cudaGetSymbolAddress((void**)&aoh, gAOh); cudaGetSymbolAddress((void**)&aol, gAOl);

    __nv_bfloat16 *wih,*wil,*wroh,*wrol,*wqh,*wql,*wkh,*wkl,*wvh,*wvl,*waoh,*waol,*wlmh,*wlml;
    cudaGetSymbolAddress((void**)&wih, gWih);   cudaGetSymbolAddress((void**)&wil, gWil);
    cudaGetSymbolAddress((void**)&wroh, gWroh); cudaGetSymbolAddress((void**)&wrol, gWrol);
    cudaGetSymbolAddress((void**)&wqh, gWqh);   cudaGetSymbolAddress((void**)&wql, gWql);
    cudaGetSymbolAddress((void**)&wkh, gWkh);   cudaGetSymbolAddress((void**)&wkl, gWkl);
    cudaGetSymbolAddress((void**)&wvh, gWvh);   cudaGetSymbolAddress((void**)&wvl, gWvl);
    cudaGetSymbolAddress((void**)&waoh, gWaoh); cudaGetSymbolAddress((void**)&waol, gWaol);
    cudaGetSymbolAddress((void**)&wlmh, gWlmh); cudaGetSymbolAddress((void**)&wlml, gWlml);

    long fullsz = (long)MT * Vc + 2L * MT * Hc;
    float* hidden = hidF;
    float* outs   = outsF;
    if ((long)out_size >= fullsz) {
        hidden = out + (size_t)MT * Vc;
        outs   = hidden + (size_t)MT * Hc;
    }

    const float qscale = 1.0f / sqrtf((float)Kc);

    // ---- weight conversions ----
    auto conv = [&](const float* src, __nv_bfloat16* h, __nv_bfloat16* l, long n) {
        int n4 = (int)(n / 4);
        conv_split<<<(n4 + 255) / 256, 256>>>(src, h, l, n4);
    };
    conv(Wi,  wih,  wil,  (long)Hc * Ec);
    conv(Wro, wroh, wrol, (long)Hc * Hc);
    conv(Wq,  wqh,  wql,  (long)Kc * Hc);
    conv(Wk,  wkh,  wkl,  (long)Kc * Hc);
    conv(Wv,  wvh,  wvl,  (long)Vdc * Hc);
    conv(Wao, waoh, waol, (long)Hc * Vdc);
    conv(Wlm, wlmh, wlml, (long)Vc * Hc);

    // ---- embedding gather + split ----
    gather_emb<<<MT, 128>>>(tok, emb, xh, xl);

    // ---- xp = x @ Wi^T + bi (fp32 out) ----
    gemm_mma<0><<<dim3(MT / 128, Hc / 128, 1), 128>>>(
        xh, xl, wih, wil, bi, xp, (__nv_bfloat16*)0, (__nv_bfloat16*)0,
        MT, Hc, Ec, 1.f, 0, 0, 0);

    // ---- RNN recurrence -> hidden (fp32) + hi/lo ----
    rnn_kernel<<<RNN_BLOCKS, 256>>>(xp, Wh, bh, hidden, hh, hl);

    // ---- outs = hidden @ Wro^T + bro (fp32 + hi/lo) ----
    gemm_mma<0><<<dim3(MT / 128, Hc / 128, 1), 128>>>(
        hh, hl, wroh, wrol, bro, outs, oh, ol,
        MT, Hc, Hc, 1.f, 0, 0, 0);

    // ---- q, k, v (bf16-only outputs) ----
    gemm_mma<0><<<dim3(MT / 128, Kc / 128, 1), 128>>>(
        oh, ol, wqh, wql, bq, (float*)0, qh, ql,
        MT, Kc, Hc, qscale, 0, 0, 0);
    gemm_mma<0><<<dim3(MT / 128, Kc / 128, 1), 128>>>(
        oh, ol, wkh, wkl, bk, (float*)0, kh, kl,
        MT, Kc, Hc, 1.f, 0, 0, 0);
    gemm_mma<1><<<dim3(MT / 128, Vdc / 128, 1), 128>>>(
        oh, ol, wvh, wvl, bv, (float*)0, vh, vl,
        MT, Vdc, Hc, 1.f, 0, 0, 0);

    // ---- scores[b] = q[b] @ k[b]^T (fp32 out, batched) ----
    gemm_mma<0><<<dim3(Tc / 128, Tc / 128, Bc), 128>>>(
        qh, ql, kh, kl, (const float*)0, s, (__nv_bfloat16*)0, (__nv_bfloat16*)0,
        Tc, Tc, Kc, 1.f, (long)Tc * Kc, (long)Tc * Kc, (long)Tc * Tc);

    // ---- causal softmax -> bf16 hi/lo probs ----
    softmax_causal<<<MT, 256>>>(s, sh, sl);

    // ---- attn[b] = P[b] @ v[b] via vT (bf16-only out, batched) ----
    gemm_mma<0><<<dim3(Tc / 128, Vdc / 128, Bc), 128>>>(
        sh, sl, vh, vl, (const float*)0, (float*)0, ah, al,
        Tc, Vdc, Tc, 1.f, (long)Tc * Tc, (long)Vdc * Tc, (long)Tc * Vdc);

    // ---- attn_out = attn @ Wao^T + bao (bf16-only out) ----
    gemm_mma<0><<<dim3(MT / 128, Hc / 128, 1), 128>>>(
        ah, al, waoh, waol, bao, (float*)0, aoh, aol,
        MT, Hc, Vdc, 1.f, 0, 0, 0);

    // ---- logits = attn_out @ Wlm^T + blm (fp32 out) ----
    gemm_mma<0><<<dim3(MT / 128, Vc / 128, 1), 128>>>(
        aoh, aol, wlmh, wlml, blm, out, (__nv_bfloat16*)0, (__nv_bfloat16*)0,
        MT, Vc, Hc, 1.f, 0, 0, 0);
}